// round 8
// baseline (speedup 1.0000x reference)
#include <cuda_runtime.h>
#include <cuda_bf16.h>

#define FDIM 128
#define NZERO 128          // CTAs that zero the sum region
#define PDIST 16           // L2 prefetch distance in rows

__device__ unsigned g_zero_flag;   // reset to 0 via 4-byte memset each launch

// Vector reduction (no return) into global memory.
__device__ __forceinline__ void red_add_v4(float* addr, float4 v) {
    asm volatile("red.global.add.v4.f32 [%0], {%1, %2, %3, %4};"
                 :: "l"(addr), "f"(v.x), "f"(v.y), "f"(v.z), "f"(v.w)
                 : "memory");
}

__device__ __forceinline__ void prefetch_l2(const void* p) {
    asm volatile("prefetch.global.L2 [%0];" :: "l"(p));
}

__device__ __forceinline__ float sigmoidf_fast(float x) {
    return 1.0f / (1.0f + __expf(-x));
}

// Spin (acquire) until all zeroing CTAs have released. Called only before the
// first atomic flush of a warp; zeroing CTAs are wave-1 resident -> no deadlock.
__device__ __forceinline__ void wait_zero(bool& ready, unsigned nz) {
    if (!ready) {
        unsigned v;
        for (;;) {
            asm volatile("ld.acquire.gpu.global.u32 %0, [%1];"
                         : "=r"(v) : "l"(&g_zero_flag));
            if (v >= nz) break;
            __nanosleep(64);
        }
        ready = true;
    }
}

// One warp processes CHUNK consecutive rows, unrolled by 8 for MLP, with
// deduplicated L2 prefetch at distance PDIST (lanes 0/8/16/24 each prefetch
// one 128B line -> exact row coverage, no redundant requests).
// Lane l owns features [4l, 4l+4). Sorted segments -> register accumulate,
// flush via red.global only at segment boundaries; group fast path when the
// whole 8-row group stays in the current segment.
template <int CHUNK, bool WRITE_LOGITS>
__device__ __forceinline__ void run_side(const float* __restrict__ feats,
                                         const float* __restrict__ W,
                                         const float* __restrict__ bptr,
                                         const int*   __restrict__ seg,
                                         int n_rows,
                                         float* __restrict__ out_sum,
                                         float* __restrict__ out_logits,
                                         int chunk_idx, int lane,
                                         bool& ready, unsigned nz)
{
    long row0 = (long)chunk_idx * CHUNK;
    if (row0 >= n_rows) return;
    const long row_end = min((long)n_rows, row0 + CHUNK);

    const float4 w4  = *reinterpret_cast<const float4*>(W + lane * 4);
    const float bias = __ldg(bptr);
    const bool pf_lane = ((lane & 7) == 0);

    float4 acc = make_float4(0.f, 0.f, 0.f, 0.f);
    int cur = __ldg(seg + row0);

    long r = row0;
    for (; r + 7 < row_end; r += 8) {
        // 8 independent LDG.128 issued up front.
        float4 f[8];
        #pragma unroll
        for (int i = 0; i < 8; ++i)
            f[i] = *reinterpret_cast<const float4*>(feats + (r + i) * FDIM + lane * 4);
        const int4 sa = *reinterpret_cast<const int4*>(seg + r);     // uniform, L1-hit
        const int4 sb = *reinterpret_cast<const int4*>(seg + r + 4);
        int s[8] = {sa.x, sa.y, sa.z, sa.w, sb.x, sb.y, sb.z, sb.w};

        // Dedup L2 prefetch: rows r+PDIST .. r+PDIST+7, 4 lines/row via 4 lanes.
        if (pf_lane) {
            #pragma unroll
            for (int i = 0; i < 8; ++i) {
                const long pr = r + PDIST + i;
                if (pr < (long)n_rows)
                    prefetch_l2(feats + pr * FDIM + lane * 4);
            }
        }

        float p[8];
        #pragma unroll
        for (int i = 0; i < 8; ++i)
            p[i] = f[i].x * w4.x + f[i].y * w4.y + f[i].z * w4.z + f[i].w * w4.w;

        // 8 interleaved butterfly chains: SHFL latencies overlap.
        #pragma unroll
        for (int o = 16; o > 0; o >>= 1) {
            #pragma unroll
            for (int i = 0; i < 8; ++i)
                p[i] += __shfl_xor_sync(0xffffffffu, p[i], o);
        }

        float g[8];
        #pragma unroll
        for (int i = 0; i < 8; ++i) {
            p[i] += bias;                 // logit
            g[i] = sigmoidf_fast(p[i]);
        }

        if (WRITE_LOGITS && lane == 0) {
            // r is a multiple of 8 -> 16B-aligned vector stores.
            *reinterpret_cast<float4*>(out_logits + r)     = make_float4(p[0], p[1], p[2], p[3]);
            *reinterpret_cast<float4*>(out_logits + r + 4) = make_float4(p[4], p[5], p[6], p[7]);
        }

        if (s[7] == cur) {
            // Fast path: whole group in current segment (sorted + s[i] >= cur).
            #pragma unroll
            for (int i = 0; i < 8; ++i) {
                acc.x += g[i] * f[i].x; acc.y += g[i] * f[i].y;
                acc.z += g[i] * f[i].z; acc.w += g[i] * f[i].w;
            }
        } else {
            #pragma unroll
            for (int i = 0; i < 8; ++i) {
                if (s[i] != cur) {
                    wait_zero(ready, nz);
                    red_add_v4(out_sum + (long)cur * FDIM + lane * 4, acc);
                    acc = make_float4(0.f, 0.f, 0.f, 0.f);
                    cur = s[i];
                }
                acc.x += g[i] * f[i].x; acc.y += g[i] * f[i].y;
                acc.z += g[i] * f[i].z; acc.w += g[i] * f[i].w;
            }
        }
    }
    // Scalar tail (not hit for the given shapes, kept for safety).
    for (; r < row_end; ++r) {
        const float4 fv = *reinterpret_cast<const float4*>(feats + r * FDIM + lane * 4);
        float p = fv.x * w4.x + fv.y * w4.y + fv.z * w4.z + fv.w * w4.w;
        #pragma unroll
        for (int o = 16; o > 0; o >>= 1)
            p += __shfl_xor_sync(0xffffffffu, p, o);
        const float lg = p + bias;
        if (WRITE_LOGITS && lane == 0) out_logits[r] = lg;
        const float gv = sigmoidf_fast(lg);
        const int sv = __ldg(seg + r);
        if (sv != cur) {
            wait_zero(ready, nz);
            red_add_v4(out_sum + (long)cur * FDIM + lane * 4, acc);
            acc = make_float4(0.f, 0.f, 0.f, 0.f);
            cur = sv;
        }
        acc.x += gv * fv.x; acc.y += gv * fv.y; acc.z += gv * fv.z; acc.w += gv * fv.w;
    }
    wait_zero(ready, nz);
    red_add_v4(out_sum + (long)cur * FDIM + lane * 4, acc);
}

// Single fused launch: first NZERO CTAs zero the sum region (then release a
// flag), all warps then do atom-side chunks (CHUNK=64, logits) or vir-side
// chunks (CHUNK=8).
__global__ __launch_bounds__(256, 3)
void fused_gated_segsum(const float* __restrict__ atom_feats,
                        const float* __restrict__ W_atom,
                        const float* __restrict__ b_atom,
                        const int*   __restrict__ atom_seg,
                        int n_atom, int atom_chunks,
                        const float* __restrict__ vir_feats,
                        const float* __restrict__ W_vir,
                        const float* __restrict__ b_vir,
                        const int*   __restrict__ vir_seg,
                        int n_vir, int vir_chunks,
                        float* __restrict__ sum_atom,
                        float* __restrict__ sum_vir,
                        float* __restrict__ logits,
                        unsigned num_graphs)
{
    const unsigned nz = min((unsigned)NZERO, gridDim.x);

    // First nz CTAs zero the segment-sum region, then release the flag.
    if (blockIdx.x < nz) {
        float4* sums4 = reinterpret_cast<float4*>(sum_atom);  // atom+vir contiguous
        const unsigned total_f4 = num_graphs * 64u;           // num_graphs*256 floats
        const float4 z = make_float4(0.f, 0.f, 0.f, 0.f);
        for (unsigned i = blockIdx.x * blockDim.x + threadIdx.x;
             i < total_f4; i += nz * blockDim.x)
            sums4[i] = z;
        __syncthreads();   // all block stores happen-before the release below
        if (threadIdx.x == 0)
            asm volatile("red.release.gpu.global.add.u32 [%0], 1;"
                         :: "l"(&g_zero_flag) : "memory");
    }

    const int warp = (int)((blockIdx.x * blockDim.x + threadIdx.x) >> 5);
    const int lane = threadIdx.x & 31;
    bool ready = false;

    if (warp < atom_chunks) {
        run_side<64, true>(atom_feats, W_atom, b_atom, atom_seg, n_atom,
                           sum_atom, logits, warp, lane, ready, nz);
    } else if (warp < atom_chunks + vir_chunks) {
        run_side<8, false>(vir_feats, W_vir, b_vir, vir_seg, n_vir,
                           sum_vir, nullptr, warp - atom_chunks, lane, ready, nz);
    }
}

extern "C" void kernel_launch(void* const* d_in, const int* in_sizes, int n_in,
                              void* d_out, int out_size) {
    const float* atom_feats = (const float*)d_in[0];
    const float* vir_feats  = (const float*)d_in[1];
    const float* W_atom     = (const float*)d_in[2];
    const float* b_atom     = (const float*)d_in[3];
    const float* W_vir      = (const float*)d_in[4];
    const float* b_vir      = (const float*)d_in[5];
    const int*   atom_seg   = (const int*)d_in[6];
    const int*   vir_seg    = (const int*)d_in[7];

    const int n_atom = in_sizes[0] / FDIM;
    const int n_vir  = in_sizes[1] / FDIM;
    const int num_graphs = (out_size - n_atom) / (2 * FDIM);

    float* out      = (float*)d_out;
    float* sum_atom = out;
    float* sum_vir  = out + (size_t)num_graphs * FDIM;
    float* logits   = out + (size_t)num_graphs * FDIM * 2;

    // Reset the zero-completion flag (4 bytes); bulk zeroing happens in-kernel.
    static unsigned* flag_ptr = nullptr;
    if (!flag_ptr) cudaGetSymbolAddress((void**)&flag_ptr, g_zero_flag);
    cudaMemsetAsync(flag_ptr, 0, sizeof(unsigned), 0);

    constexpr int CHUNK_A = 64;
    constexpr int CHUNK_V = 8;
    constexpr int THREADS = 256;   // 8 warps / CTA

    const int atom_chunks = (n_atom + CHUNK_A - 1) / CHUNK_A;
    const int vir_chunks  = (n_vir  + CHUNK_V - 1) / CHUNK_V;
    const int total_warps = atom_chunks + vir_chunks;
    const int blocks = (total_warps + 7) / 8;

    fused_gated_segsum<<<blocks, THREADS>>>(
        atom_feats, W_atom, b_atom, atom_seg, n_atom, atom_chunks,
        vir_feats,  W_vir,  b_vir,  vir_seg,  n_vir,  vir_chunks,
        sum_atom, sum_vir, logits, (unsigned)num_graphs);
}

// round 9
// speedup vs baseline: 1.0127x; 1.0127x over previous
#include <cuda_runtime.h>
#include <cuda_bf16.h>

#define FDIM 128
#define PDIST 8            // L2 prefetch distance in rows

// Vector reduction (no return) into global memory.
__device__ __forceinline__ void red_add_v4(float* addr, float4 v) {
    asm volatile("red.global.add.v4.f32 [%0], {%1, %2, %3, %4};"
                 :: "l"(addr), "f"(v.x), "f"(v.y), "f"(v.z), "f"(v.w)
                 : "memory");
}

__device__ __forceinline__ void prefetch_l2(const void* p) {
    asm volatile("prefetch.global.L2 [%0];" :: "l"(p));
}

// Streaming store (evict-first) for outputs we never re-read.
__device__ __forceinline__ void stg_cs_v4(float* addr, float4 v) {
    asm volatile("st.global.cs.v4.f32 [%0], {%1, %2, %3, %4};"
                 :: "l"(addr), "f"(v.x), "f"(v.y), "f"(v.z), "f"(v.w)
                 : "memory");
}

__device__ __forceinline__ float sigmoidf_fast(float x) {
    return 1.0f / (1.0f + __expf(-x));
}

// One warp processes CHUNK consecutive rows, unrolled by 4 (measured-best:
// 64 regs -> 4 CTAs/SM). Lane l owns features [4l, 4l+4). L2 prefetch at
// distance PDIST keeps DRAM reads in flight during the shuffle/compute phase.
// Sorted segments -> register accumulate, flush via red.global only at
// segment boundaries (group fast path when all 4 rows stay).
template <int CHUNK, bool WRITE_LOGITS>
__device__ __forceinline__ void run_side(const float* __restrict__ feats,
                                         const float* __restrict__ W,
                                         const float* __restrict__ bptr,
                                         const int*   __restrict__ seg,
                                         int n_rows,
                                         float* __restrict__ out_sum,
                                         float* __restrict__ out_logits,
                                         int chunk_idx, int lane)
{
    long row0 = (long)chunk_idx * CHUNK;
    if (row0 >= n_rows) return;
    const long row_end = min((long)n_rows, row0 + CHUNK);

    const float4 w4  = *reinterpret_cast<const float4*>(W + lane * 4);
    const float bias = __ldg(bptr);

    float4 acc = make_float4(0.f, 0.f, 0.f, 0.f);
    int cur = __ldg(seg + row0);

    long r = row0;
    // Unrolled-by-4 main body: 4 independent load+reduce chains in flight.
    for (; r + 3 < row_end; r += 4) {
        const float4 f0 = *reinterpret_cast<const float4*>(feats + (r + 0) * FDIM + lane * 4);
        const float4 f1 = *reinterpret_cast<const float4*>(feats + (r + 1) * FDIM + lane * 4);
        const float4 f2 = *reinterpret_cast<const float4*>(feats + (r + 2) * FDIM + lane * 4);
        const float4 f3 = *reinterpret_cast<const float4*>(feats + (r + 3) * FDIM + lane * 4);
        const int4  s4  = *reinterpret_cast<const int4*>(seg + r);   // uniform, L1-hit

        // Prefetch rows r+PDIST .. r+PDIST+3 into L2 (no regs, no scoreboard).
        #pragma unroll
        for (int i = 0; i < 4; ++i) {
            const long pr = r + PDIST + i;
            if (pr < (long)n_rows)
                prefetch_l2(feats + pr * FDIM + lane * 4);
        }

        float p0 = f0.x * w4.x + f0.y * w4.y + f0.z * w4.z + f0.w * w4.w;
        float p1 = f1.x * w4.x + f1.y * w4.y + f1.z * w4.z + f1.w * w4.w;
        float p2 = f2.x * w4.x + f2.y * w4.y + f2.z * w4.z + f2.w * w4.w;
        float p3 = f3.x * w4.x + f3.y * w4.y + f3.z * w4.z + f3.w * w4.w;

        // 4 interleaved butterfly chains: SHFL latencies overlap across rows.
        #pragma unroll
        for (int o = 16; o > 0; o >>= 1) {
            p0 += __shfl_xor_sync(0xffffffffu, p0, o);
            p1 += __shfl_xor_sync(0xffffffffu, p1, o);
            p2 += __shfl_xor_sync(0xffffffffu, p2, o);
            p3 += __shfl_xor_sync(0xffffffffu, p3, o);
        }

        const float l0 = p0 + bias, l1 = p1 + bias, l2 = p2 + bias, l3 = p3 + bias;
        if (WRITE_LOGITS && lane == 0) {
            // r is a multiple of 4 -> 16B-aligned streaming store.
            stg_cs_v4(out_logits + r, make_float4(l0, l1, l2, l3));
        }
        const float g0 = sigmoidf_fast(l0);
        const float g1 = sigmoidf_fast(l1);
        const float g2 = sigmoidf_fast(l2);
        const float g3 = sigmoidf_fast(l3);

        if (s4.w == cur) {
            // Fast path: whole group in current segment (seg sorted, s >= cur).
            acc.x += g0 * f0.x; acc.y += g0 * f0.y; acc.z += g0 * f0.z; acc.w += g0 * f0.w;
            acc.x += g1 * f1.x; acc.y += g1 * f1.y; acc.z += g1 * f1.z; acc.w += g1 * f1.w;
            acc.x += g2 * f2.x; acc.y += g2 * f2.y; acc.z += g2 * f2.z; acc.w += g2 * f2.w;
            acc.x += g3 * f3.x; acc.y += g3 * f3.y; acc.z += g3 * f3.z; acc.w += g3 * f3.w;
        } else {
            if (s4.x != cur) { red_add_v4(out_sum + (long)cur * FDIM + lane * 4, acc);
                               acc = make_float4(0.f,0.f,0.f,0.f); cur = s4.x; }
            acc.x += g0 * f0.x; acc.y += g0 * f0.y; acc.z += g0 * f0.z; acc.w += g0 * f0.w;
            if (s4.y != cur) { red_add_v4(out_sum + (long)cur * FDIM + lane * 4, acc);
                               acc = make_float4(0.f,0.f,0.f,0.f); cur = s4.y; }
            acc.x += g1 * f1.x; acc.y += g1 * f1.y; acc.z += g1 * f1.z; acc.w += g1 * f1.w;
            if (s4.z != cur) { red_add_v4(out_sum + (long)cur * FDIM + lane * 4, acc);
                               acc = make_float4(0.f,0.f,0.f,0.f); cur = s4.z; }
            acc.x += g2 * f2.x; acc.y += g2 * f2.y; acc.z += g2 * f2.z; acc.w += g2 * f2.w;
            if (s4.w != cur) { red_add_v4(out_sum + (long)cur * FDIM + lane * 4, acc);
                               acc = make_float4(0.f,0.f,0.f,0.f); cur = s4.w; }
            acc.x += g3 * f3.x; acc.y += g3 * f3.y; acc.z += g3 * f3.z; acc.w += g3 * f3.w;
        }
    }
    // Scalar tail (not hit for the given shapes, kept for safety).
    for (; r < row_end; ++r) {
        const float4 f = *reinterpret_cast<const float4*>(feats + r * FDIM + lane * 4);
        float p = f.x * w4.x + f.y * w4.y + f.z * w4.z + f.w * w4.w;
        #pragma unroll
        for (int o = 16; o > 0; o >>= 1)
            p += __shfl_xor_sync(0xffffffffu, p, o);
        const float lg = p + bias;
        if (WRITE_LOGITS && lane == 0) out_logits[r] = lg;
        const float g = sigmoidf_fast(lg);
        const int s = __ldg(seg + r);
        if (s != cur) { red_add_v4(out_sum + (long)cur * FDIM + lane * 4, acc);
                        acc = make_float4(0.f,0.f,0.f,0.f); cur = s; }
        acc.x += g * f.x; acc.y += g * f.y; acc.z += g * f.z; acc.w += g * f.w;
    }
    red_add_v4(out_sum + (long)cur * FDIM + lane * 4, acc);
}

// Single fused launch: warps [0, atomChunks) do the atom side (CHUNK=64, logits),
// warps [atomChunks, atomChunks+virChunks) do the vir side (CHUNK=8).
__global__ __launch_bounds__(256, 4)
void fused_gated_segsum(const float* __restrict__ atom_feats,
                        const float* __restrict__ W_atom,
                        const float* __restrict__ b_atom,
                        const int*   __restrict__ atom_seg,
                        int n_atom, int atom_chunks,
                        const float* __restrict__ vir_feats,
                        const float* __restrict__ W_vir,
                        const float* __restrict__ b_vir,
                        const int*   __restrict__ vir_seg,
                        int n_vir, int vir_chunks,
                        float* __restrict__ sum_atom,
                        float* __restrict__ sum_vir,
                        float* __restrict__ logits)
{
    const int warp = (int)((blockIdx.x * blockDim.x + threadIdx.x) >> 5);
    const int lane = threadIdx.x & 31;

    if (warp < atom_chunks) {
        run_side<64, true>(atom_feats, W_atom, b_atom, atom_seg, n_atom,
                           sum_atom, logits, warp, lane);
    } else if (warp < atom_chunks + vir_chunks) {
        run_side<8, false>(vir_feats, W_vir, b_vir, vir_seg, n_vir,
                           sum_vir, nullptr, warp - atom_chunks, lane);
    }
}

extern "C" void kernel_launch(void* const* d_in, const int* in_sizes, int n_in,
                              void* d_out, int out_size) {
    const float* atom_feats = (const float*)d_in[0];
    const float* vir_feats  = (const float*)d_in[1];
    const float* W_atom     = (const float*)d_in[2];
    const float* b_atom     = (const float*)d_in[3];
    const float* W_vir      = (const float*)d_in[4];
    const float* b_vir      = (const float*)d_in[5];
    const int*   atom_seg   = (const int*)d_in[6];
    const int*   vir_seg    = (const int*)d_in[7];

    const int n_atom = in_sizes[0] / FDIM;
    const int n_vir  = in_sizes[1] / FDIM;
    const int num_graphs = (out_size - n_atom) / (2 * FDIM);

    float* out      = (float*)d_out;
    float* sum_atom = out;
    float* sum_vir  = out + (size_t)num_graphs * FDIM;
    float* logits   = out + (size_t)num_graphs * FDIM * 2;

    // Zero only the segment-sum regions (logits fully overwritten).
    cudaMemsetAsync(out, 0, (size_t)num_graphs * FDIM * 2 * sizeof(float), 0);

    constexpr int CHUNK_A = 64;
    constexpr int CHUNK_V = 8;
    constexpr int THREADS = 256;   // 8 warps / CTA

    const int atom_chunks = (n_atom + CHUNK_A - 1) / CHUNK_A;
    const int vir_chunks  = (n_vir  + CHUNK_V - 1) / CHUNK_V;
    const int total_warps = atom_chunks + vir_chunks;
    const int blocks = (total_warps + 7) / 8;

    fused_gated_segsum<<<blocks, THREADS>>>(
        atom_feats, W_atom, b_atom, atom_seg, n_atom, atom_chunks,
        vir_feats,  W_vir,  b_vir,  vir_seg,  n_vir,  vir_chunks,
        sum_atom, sum_vir, logits);
}

// round 11
// speedup vs baseline: 1.0610x; 1.0477x over previous
#include <cuda_runtime.h>
#include <cuda_bf16.h>

#define FDIM 128
#define PDIST 8            // L2 prefetch distance in rows
#define MAXG  (1 << 20)    // max supported num_graphs for the boundary scratch

// Scratch: bound[g] = first row index with seg >= g (per side).
__device__ int g_bound_atom[MAXG + 2];
__device__ int g_bound_vir [MAXG + 2];

__device__ __forceinline__ void prefetch_l2(const void* p) {
    asm volatile("prefetch.global.L2 [%0];" :: "l"(p));
}

// Streaming scalar store (evict-first) for write-once outputs.
__device__ __forceinline__ void stg_cs_f32(float* addr, float v) {
    asm volatile("st.global.cs.f32 [%0], %1;" :: "l"(addr), "f"(v) : "memory");
}
__device__ __forceinline__ void stg_cs_v4(float* addr, float4 v) {
    asm volatile("st.global.cs.v4.f32 [%0], {%1, %2, %3, %4};"
                 :: "l"(addr), "f"(v.x), "f"(v.y), "f"(v.z), "f"(v.w)
                 : "memory");
}

__device__ __forceinline__ float sigmoidf_fast(float x) {
    return 1.0f / (1.0f + __expf(-x));
}

// ---------------------------------------------------------------------------
// Kernel 1: segment boundaries. Thread per row; row i writes bound[g] = i for
// every g in (seg[i-1], seg[i]] (seg[-1] := -1). Last row fills the tail with
// n_rows. Each bound slot is written by exactly one thread -> race-free.
// ---------------------------------------------------------------------------
__global__ void boundary_kernel(const int* __restrict__ atom_seg, int n_atom,
                                const int* __restrict__ vir_seg,  int n_vir,
                                int num_graphs)
{
    const int i = blockIdx.x * blockDim.x + threadIdx.x;
    if (i < n_atom) {
        const int s  = atom_seg[i];
        const int sp = (i == 0) ? -1 : atom_seg[i - 1];
        for (int g = sp + 1; g <= s; ++g) g_bound_atom[g] = i;
        if (i == n_atom - 1)
            for (int g = s + 1; g <= num_graphs; ++g) g_bound_atom[g] = n_atom;
    } else {
        const int j = i - n_atom;
        if (j < n_vir) {
            const int s  = vir_seg[j];
            const int sp = (j == 0) ? -1 : vir_seg[j - 1];
            for (int g = sp + 1; g <= s; ++g) g_bound_vir[g] = j;
            if (j == n_vir - 1)
                for (int g = s + 1; g <= num_graphs; ++g) g_bound_vir[g] = n_vir;
        }
    }
}

// ---------------------------------------------------------------------------
// Kernel 2: one warp owns whole graphs. Rows [bound[g], bound[g+1]) are summed
// in registers (unroll 4 + L2 prefetch) and the 128-float result is stored
// ONCE with a plain coalesced store -> no memset, no atomics, no seg loads.
// Lane l owns features [4l, 4l+4).
// ---------------------------------------------------------------------------
template <bool WRITE_LOGITS>
__device__ __forceinline__ void do_graph(const float* __restrict__ feats,
                                         const float4 w4, const float bias,
                                         int r0, int r1, int n_rows,
                                         float* __restrict__ out_sum_g,
                                         float* __restrict__ out_logits,
                                         int lane)
{
    float4 acc = make_float4(0.f, 0.f, 0.f, 0.f);

    int r = r0;
    for (; r + 3 < r1; r += 4) {
        const float4 f0 = *reinterpret_cast<const float4*>(feats + (size_t)(r + 0) * FDIM + lane * 4);
        const float4 f1 = *reinterpret_cast<const float4*>(feats + (size_t)(r + 1) * FDIM + lane * 4);
        const float4 f2 = *reinterpret_cast<const float4*>(feats + (size_t)(r + 2) * FDIM + lane * 4);
        const float4 f3 = *reinterpret_cast<const float4*>(feats + (size_t)(r + 3) * FDIM + lane * 4);

        // Prefetch rows r+PDIST .. r+PDIST+3 into L2 (predicated on global end;
        // spilling into the next graph's rows is still useful work).
        #pragma unroll
        for (int i = 0; i < 4; ++i) {
            const int pr = r + PDIST + i;
            if (pr < n_rows)
                prefetch_l2(feats + (size_t)pr * FDIM + lane * 4);
        }

        float p0 = f0.x * w4.x + f0.y * w4.y + f0.z * w4.z + f0.w * w4.w;
        float p1 = f1.x * w4.x + f1.y * w4.y + f1.z * w4.z + f1.w * w4.w;
        float p2 = f2.x * w4.x + f2.y * w4.y + f2.z * w4.z + f2.w * w4.w;
        float p3 = f3.x * w4.x + f3.y * w4.y + f3.z * w4.z + f3.w * w4.w;

        #pragma unroll
        for (int o = 16; o > 0; o >>= 1) {
            p0 += __shfl_xor_sync(0xffffffffu, p0, o);
            p1 += __shfl_xor_sync(0xffffffffu, p1, o);
            p2 += __shfl_xor_sync(0xffffffffu, p2, o);
            p3 += __shfl_xor_sync(0xffffffffu, p3, o);
        }
        p0 += bias; p1 += bias; p2 += bias; p3 += bias;

        if (WRITE_LOGITS && lane == 0) {
            stg_cs_f32(out_logits + r + 0, p0);
            stg_cs_f32(out_logits + r + 1, p1);
            stg_cs_f32(out_logits + r + 2, p2);
            stg_cs_f32(out_logits + r + 3, p3);
        }

        const float g0 = sigmoidf_fast(p0);
        const float g1 = sigmoidf_fast(p1);
        const float g2 = sigmoidf_fast(p2);
        const float g3 = sigmoidf_fast(p3);

        acc.x += g0 * f0.x; acc.y += g0 * f0.y; acc.z += g0 * f0.z; acc.w += g0 * f0.w;
        acc.x += g1 * f1.x; acc.y += g1 * f1.y; acc.z += g1 * f1.z; acc.w += g1 * f1.w;
        acc.x += g2 * f2.x; acc.y += g2 * f2.y; acc.z += g2 * f2.z; acc.w += g2 * f2.w;
        acc.x += g3 * f3.x; acc.y += g3 * f3.y; acc.z += g3 * f3.z; acc.w += g3 * f3.w;
    }
    for (; r < r1; ++r) {
        const float4 f = *reinterpret_cast<const float4*>(feats + (size_t)r * FDIM + lane * 4);
        float p = f.x * w4.x + f.y * w4.y + f.z * w4.z + f.w * w4.w;
        #pragma unroll
        for (int o = 16; o > 0; o >>= 1)
            p += __shfl_xor_sync(0xffffffffu, p, o);
        p += bias;
        if (WRITE_LOGITS && lane == 0) stg_cs_f32(out_logits + r, p);
        const float g = sigmoidf_fast(p);
        acc.x += g * f.x; acc.y += g * f.y; acc.z += g * f.z; acc.w += g * f.w;
    }

    // Exactly-once coalesced result store (512B per warp). Empty graph -> zeros.
    stg_cs_v4(out_sum_g + lane * 4, acc);
}

#define GPW 2   // graphs per warp (balance: atom ~100 rows/warp, +-10%)

__global__ __launch_bounds__(256)
void fused_gated_segsum(const float* __restrict__ atom_feats,
                        const float* __restrict__ W_atom,
                        const float* __restrict__ b_atom,
                        int n_atom,
                        const float* __restrict__ vir_feats,
                        const float* __restrict__ W_vir,
                        const float* __restrict__ b_vir,
                        int n_vir,
                        int num_graphs,
                        float* __restrict__ sum_atom,
                        float* __restrict__ sum_vir,
                        float* __restrict__ logits)
{
    const int warp = (int)((blockIdx.x * blockDim.x + threadIdx.x) >> 5);
    const int lane = threadIdx.x & 31;

    const int atom_groups = (num_graphs + GPW - 1) / GPW;
    const int vir_groups  = atom_groups;

    if (warp < atom_groups) {
        const float4 w4  = *reinterpret_cast<const float4*>(W_atom + lane * 4);
        const float bias = __ldg(b_atom);
        const int g0 = warp * GPW;
        const int g1 = min(num_graphs, g0 + GPW);
        int rs = g_bound_atom[g0];
        for (int g = g0; g < g1; ++g) {
            const int re = g_bound_atom[g + 1];
            do_graph<true>(atom_feats, w4, bias, rs, re, n_atom,
                           sum_atom + (size_t)g * FDIM, logits, lane);
            rs = re;
        }
    } else if (warp < atom_groups + vir_groups) {
        const int w = warp - atom_groups;
        const float4 w4  = *reinterpret_cast<const float4*>(W_vir + lane * 4);
        const float bias = __ldg(b_vir);
        const int g0 = w * GPW;
        const int g1 = min(num_graphs, g0 + GPW);
        if (g0 < num_graphs) {
            int rs = g_bound_vir[g0];
            for (int g = g0; g < g1; ++g) {
                const int re = g_bound_vir[g + 1];
                do_graph<false>(vir_feats, w4, bias, rs, re, n_vir,
                                sum_vir + (size_t)g * FDIM, nullptr, lane);
                rs = re;
            }
        }
    }
}

extern "C" void kernel_launch(void* const* d_in, const int* in_sizes, int n_in,
                              void* d_out, int out_size) {
    const float* atom_feats = (const float*)d_in[0];
    const float* vir_feats  = (const float*)d_in[1];
    const float* W_atom     = (const float*)d_in[2];
    const float* b_atom     = (const float*)d_in[3];
    const float* W_vir      = (const float*)d_in[4];
    const float* b_vir      = (const float*)d_in[5];
    const int*   atom_seg   = (const int*)d_in[6];
    const int*   vir_seg    = (const int*)d_in[7];

    const int n_atom = in_sizes[0] / FDIM;
    const int n_vir  = in_sizes[1] / FDIM;
    const int num_graphs = (out_size - n_atom) / (2 * FDIM);

    float* out      = (float*)d_out;
    float* sum_atom = out;
    float* sum_vir  = out + (size_t)num_graphs * FDIM;
    float* logits   = out + (size_t)num_graphs * FDIM * 2;

    // Kernel 1: segment boundaries (no memset needed anywhere).
    {
        const int total = n_atom + n_vir;
        boundary_kernel<<<(total + 255) / 256, 256>>>(
            atom_seg, n_atom, vir_seg, n_vir, num_graphs);
    }

    // Kernel 2: graph-owned gated sums + logits, write-once outputs.
    {
        const int atom_groups = (num_graphs + GPW - 1) / GPW;
        const int total_warps = 2 * atom_groups;
        const int blocks = (total_warps + 7) / 8;   // 8 warps / CTA
        fused_gated_segsum<<<blocks, 256>>>(
            atom_feats, W_atom, b_atom, n_atom,
            vir_feats,  W_vir,  b_vir,  n_vir,
            num_graphs, sum_atom, sum_vir, logits);
    }
}